// round 3
// baseline (speedup 1.0000x reference)
#include <cuda_runtime.h>

// ComplexScaling: separable bilinear grid_sample, s = 1 + theta[0],
// align_corners=False, zeros padding. input [32,1024,1024,2] fp32 NHWC.
//
// Prologue kernel computes g_identity = (s == 1.0f). When s == 1.0f the
// sampling map is exactly the identity in fp32 (every intermediate op is an
// exact power-of-two scaling of small integers), so the main kernel takes a
// pure 64B-per-thread copy path (4x LDG.128 / STG.128, MLP=4).
// Otherwise it runs the generic 4-corner bilinear per pixel.

#define HH 1024
#define WW 1024
#define NPIX (32 * HH * WW)          // total float2 pixels
#define PIX_PER_THREAD 8             // 8 float2 = 64 bytes per thread

__device__ int g_identity;
__device__ float g_scale;

__global__ void flag_kernel(const float* __restrict__ theta)
{
    const float s = 1.0f + theta[0];
    g_scale = s;
    g_identity = (s == 1.0f) ? 1 : 0;
}

__device__ __forceinline__ float2 bilinear_pixel(const float2* __restrict__ img,
                                                 int j, float s,
                                                 float mwy0, float mwy1,
                                                 int cy0, int cy1)
{
    const float xn = (2.0f * (float)j + 1.0f) * (1.0f / (float)WW) - 1.0f;
    const float ix = ((s * xn + 1.0f) * (float)WW - 1.0f) * 0.5f;
    const float fx0 = floorf(ix);
    const float wx1 = ix - fx0;
    const float wx0 = 1.0f - wx1;
    const int x0 = (int)fx0;
    const int x1 = x0 + 1;
    const float mwx0 = (x0 >= 0 && x0 < WW) ? wx0 : 0.0f;
    const float mwx1 = (x1 >= 0 && x1 < WW) ? wx1 : 0.0f;
    const int cx0 = min(max(x0, 0), WW - 1);
    const int cx1 = min(max(x1, 0), WW - 1);

    const float2 p00 = __ldg(img + (size_t)cy0 * WW + cx0);
    const float2 p01 = __ldg(img + (size_t)cy0 * WW + cx1);
    const float2 p10 = __ldg(img + (size_t)cy1 * WW + cx0);
    const float2 p11 = __ldg(img + (size_t)cy1 * WW + cx1);

    const float r0x = mwx0 * p00.x + mwx1 * p01.x;
    const float r0y = mwx0 * p00.y + mwx1 * p01.y;
    const float r1x = mwx0 * p10.x + mwx1 * p11.x;
    const float r1y = mwx0 * p10.y + mwx1 * p11.y;
    float2 r;
    r.x = mwy0 * r0x + mwy1 * r1x;
    r.y = mwy0 * r0y + mwy1 * r1y;
    return r;
}

__global__ __launch_bounds__(256)
void complex_scaling_kernel(const float2* __restrict__ in,
                            float2* __restrict__ out)
{
    const int t = blockIdx.x * blockDim.x + threadIdx.x;   // 64B chunk index

    if (g_identity) {
        // ---- identity copy: 4 independent 16B loads/stores (MLP=4) ----
        const float4* __restrict__ src = reinterpret_cast<const float4*>(in) + (size_t)t * 4;
        float4* __restrict__ dst       = reinterpret_cast<float4*>(out) + (size_t)t * 4;
        const float4 v0 = __ldg(src + 0);
        const float4 v1 = __ldg(src + 1);
        const float4 v2 = __ldg(src + 2);
        const float4 v3 = __ldg(src + 3);
        dst[0] = v0;
        dst[1] = v1;
        dst[2] = v2;
        dst[3] = v3;
        return;
    }

    // ---- generic bilinear path ----
    const float s = g_scale;
    const int p  = t * PIX_PER_THREAD;        // first pixel of this chunk
    const int n  = p >> 20;                   // / (HH*WW)
    const int rem = p & (HH * WW - 1);
    const int i  = rem >> 10;                 // row
    const int j0 = rem & (WW - 1);            // first column

    const float yn  = (2.0f * (float)i + 1.0f) * (1.0f / (float)HH) - 1.0f;
    const float iy  = ((s * yn + 1.0f) * (float)HH - 1.0f) * 0.5f;
    const float fy0 = floorf(iy);
    const float wy1 = iy - fy0;
    const float wy0 = 1.0f - wy1;
    const int y0 = (int)fy0;
    const int y1 = y0 + 1;
    const float mwy0 = (y0 >= 0 && y0 < HH) ? wy0 : 0.0f;
    const float mwy1 = (y1 >= 0 && y1 < HH) ? wy1 : 0.0f;
    const int cy0 = min(max(y0, 0), HH - 1);
    const int cy1 = min(max(y1, 0), HH - 1);

    const float2* img = in + (size_t)n * (HH * WW);
    float2* dst = out + (size_t)n * (HH * WW) + (size_t)i * WW + j0;

    #pragma unroll 1
    for (int k = 0; k < PIX_PER_THREAD; k++) {
        dst[k] = bilinear_pixel(img, j0 + k, s, mwy0, mwy1, cy0, cy1);
    }
}

extern "C" void kernel_launch(void* const* d_in, const int* in_sizes, int n_in,
                              void* d_out, int out_size)
{
    const float2* in   = (const float2*)d_in[0];   // [32,1024,1024,2] fp32
    const float* theta = (const float*)d_in[1];    // [1] fp32
    float2* out        = (float2*)d_out;

    flag_kernel<<<1, 1>>>(theta);

    const int threads = NPIX / PIX_PER_THREAD;     // 4,194,304
    complex_scaling_kernel<<<threads / 256, 256>>>(in, out);
}

// round 4
// speedup vs baseline: 1.0952x; 1.0952x over previous
#include <cuda_runtime.h>

// ComplexScaling: separable bilinear grid_sample, s = 1 + theta[0],
// align_corners=False, zeros padding. input [32,1024,1024,2] fp32 NHWC.
//
// Single kernel. Each thread owns one float4 (= 2 float2 pixels, 16B).
// s == 1.0f  ->  sampling map is exactly identity in fp32 (all intermediate
// scalings are exact powers of two on small integers), so take a pure
// linear-copy path: one L2::256B-hinted 16B load + one 16B store.
// Otherwise: generic 4-corner bilinear for the 2 pixels (verified in R1/R2).

#define HH 1024
#define WW 1024
#define NPIX (32 * HH * WW)   // total float2 pixels = 33,554,432

__device__ __forceinline__ float4 ldg_256hint(const float4* p)
{
    float4 v;
    asm volatile("ld.global.nc.L2::256B.v4.f32 {%0,%1,%2,%3}, [%4];"
                 : "=f"(v.x), "=f"(v.y), "=f"(v.z), "=f"(v.w)
                 : "l"(p));
    return v;
}

__global__ __launch_bounds__(256)
void complex_scaling_kernel(const float2* __restrict__ in,
                            const float* __restrict__ theta,
                            float2* __restrict__ out)
{
    const int t = blockIdx.x * blockDim.x + threadIdx.x;   // float4 index
    const float s = 1.0f + __ldg(theta);

    if (s == 1.0f) {
        // ---- identity: pure streaming copy, 16B per thread ----
        const float4 v = ldg_256hint(reinterpret_cast<const float4*>(in) + t);
        reinterpret_cast<float4*>(out)[t] = v;
        return;
    }

    // ---- generic bilinear path (2 pixels per thread) ----
    const int p   = t * 2;                 // first pixel index
    const int n   = p >> 20;               // / (HH*WW)
    const int rem = p & (HH * WW - 1);
    const int i   = rem >> 10;             // row
    const int j0  = rem & (WW - 1);        // first column
    const int j1  = j0 + 1;

    // y coords
    const float yn  = (2.0f * (float)i + 1.0f) * (1.0f / (float)HH) - 1.0f;
    const float iy  = ((s * yn + 1.0f) * (float)HH - 1.0f) * 0.5f;
    const float fy0 = floorf(iy);
    const float wy1 = iy - fy0;
    const float wy0 = 1.0f - wy1;
    const int y0 = (int)fy0;
    const int y1 = y0 + 1;
    const float mwy0 = (y0 >= 0 && y0 < HH) ? wy0 : 0.0f;
    const float mwy1 = (y1 >= 0 && y1 < HH) ? wy1 : 0.0f;
    const int cy0 = min(max(y0, 0), HH - 1);
    const int cy1 = min(max(y1, 0), HH - 1);

    // x coords for the two pixels
    const float xn0 = (2.0f * (float)j0 + 1.0f) * (1.0f / (float)WW) - 1.0f;
    const float xn1 = (2.0f * (float)j1 + 1.0f) * (1.0f / (float)WW) - 1.0f;
    const float ixa = ((s * xn0 + 1.0f) * (float)WW - 1.0f) * 0.5f;
    const float ixb = ((s * xn1 + 1.0f) * (float)WW - 1.0f) * 0.5f;
    const float fxa0 = floorf(ixa);
    const float fxb0 = floorf(ixb);
    const float wxa1 = ixa - fxa0;
    const float wxb1 = ixb - fxb0;
    const float wxa0 = 1.0f - wxa1;
    const float wxb0 = 1.0f - wxb1;
    const int xa0 = (int)fxa0;
    const int xb0 = (int)fxb0;
    const int xa1 = xa0 + 1;
    const int xb1 = xb0 + 1;

    const float mwxa0 = (xa0 >= 0 && xa0 < WW) ? wxa0 : 0.0f;
    const float mwxa1 = (xa1 >= 0 && xa1 < WW) ? wxa1 : 0.0f;
    const float mwxb0 = (xb0 >= 0 && xb0 < WW) ? wxb0 : 0.0f;
    const float mwxb1 = (xb1 >= 0 && xb1 < WW) ? wxb1 : 0.0f;
    const int cxa0 = min(max(xa0, 0), WW - 1);
    const int cxa1 = min(max(xa1, 0), WW - 1);
    const int cxb0 = min(max(xb0, 0), WW - 1);
    const int cxb1 = min(max(xb1, 0), WW - 1);

    const float2* img = in + (size_t)n * (HH * WW);
    const float2* r0  = img + (size_t)cy0 * WW;
    const float2* r1  = img + (size_t)cy1 * WW;

    const float2 a00 = __ldg(r0 + cxa0);
    const float2 a01 = __ldg(r0 + cxa1);
    const float2 a10 = __ldg(r1 + cxa0);
    const float2 a11 = __ldg(r1 + cxa1);
    const float2 b00 = __ldg(r0 + cxb0);
    const float2 b01 = __ldg(r0 + cxb1);
    const float2 b10 = __ldg(r1 + cxb0);
    const float2 b11 = __ldg(r1 + cxb1);

    float4 res;
    {
        const float r0x = mwxa0 * a00.x + mwxa1 * a01.x;
        const float r0y = mwxa0 * a00.y + mwxa1 * a01.y;
        const float r1x = mwxa0 * a10.x + mwxa1 * a11.x;
        const float r1y = mwxa0 * a10.y + mwxa1 * a11.y;
        res.x = mwy0 * r0x + mwy1 * r1x;
        res.y = mwy0 * r0y + mwy1 * r1y;
    }
    {
        const float r0x = mwxb0 * b00.x + mwxb1 * b01.x;
        const float r0y = mwxb0 * b00.y + mwxb1 * b01.y;
        const float r1x = mwxb0 * b10.x + mwxb1 * b11.x;
        const float r1y = mwxb0 * b10.y + mwxb1 * b11.y;
        res.z = mwy0 * r0x + mwy1 * r1x;
        res.w = mwy0 * r0y + mwy1 * r1y;
    }
    reinterpret_cast<float4*>(out)[t] = res;
}

extern "C" void kernel_launch(void* const* d_in, const int* in_sizes, int n_in,
                              void* d_out, int out_size)
{
    const float2* in   = (const float2*)d_in[0];   // [32,1024,1024,2] fp32
    const float* theta = (const float*)d_in[1];    // [1] fp32
    float2* out        = (float2*)d_out;

    const int threads = NPIX / 2;                  // one float4 per thread
    complex_scaling_kernel<<<threads / 256, 256>>>(in, theta, out);
}